// round 1
// baseline (speedup 1.0000x reference)
#include <cuda_runtime.h>
#include <cstdint>

#define TT   5888   // N*46 tokens
#define CC   512    // channels
#define CI   256    // inner dim
#define NBB  128    // batch N
#define NJ   46     // block size

// ---------------- scratch (device globals; no allocation allowed) ----------------
__device__ float g_feat[(size_t)TT * CC];    // BN+ReLU feature, (T, 512)
__device__ float g_proj[(size_t)TT * 768];   // [x_theta | x_phi | g_x], (T, 768)
__device__ float g_y[(size_t)TT * CI];       // y = P @ g_x, (T, 256)

// ---------------- packed f32x2 helpers (sm_103a) ----------------
__device__ __forceinline__ unsigned long long bcast2(float x) {
    unsigned long long d;
    asm("mov.b64 %0, {%1, %1};" : "=l"(d) : "r"(__float_as_uint(x)));
    return d;
}
__device__ __forceinline__ void fma2(unsigned long long& d, unsigned long long a, unsigned long long b) {
    asm("fma.rn.f32x2 %0, %1, %2, %3;" : "=l"(d) : "l"(a), "l"(b), "l"(d));
}
__device__ __forceinline__ float2 unpk(unsigned long long v) {
    unsigned int lo, hi;
    asm("mov.b64 {%0, %1}, %2;" : "=r"(lo), "=r"(hi) : "l"(v));
    return make_float2(__uint_as_float(lo), __uint_as_float(hi));
}

// ---------------- shared GEMM tile loop ----------------
// C[128 x BN] += A[128 x K] * B^T or B, fp32, f32x2 inner product.
// BNT=true : B is row-major [N x K] (NT gemm, K contiguous)
// BNT=false: B is row-major [K x N] (NN gemm, N contiguous)
// A points at tile row 0, B at tile (row n0 for NT / col n0 for NN).
// 256 threads; per-thread 8 x (BN/16) micro-tile; gmem->reg prefetch pipeline.
template<int BN, bool BNT>
__device__ __forceinline__ void gemm_tile_loop(
    const float* __restrict__ A, int lda,
    const float* __restrict__ B, int ldb, int K,
    float (*As)[128], float (*Bs)[BN],
    unsigned long long (*acc)[BN / 32], int tid)
{
    const int NP = BN / 32;      // u64 accumulator pairs per thread per row
    const int BR = BN / 64;      // B float4 loads per thread
    const int trow = (tid >> 4) * 8;
    const int tcol = (tid & 15) * (BN / 16);

    float4 pa[2], pb[BR];

    auto gload = [&](int k0) {
#pragma unroll
        for (int r = 0; r < 2; r++) {
            int f = tid + r * 256;
            pa[r] = *(const float4*)(A + (size_t)(f >> 2) * lda + k0 + ((f & 3) << 2));
        }
        if (BNT) {
#pragma unroll
            for (int r = 0; r < BR; r++) {
                int f = tid + r * 256;
                pb[r] = *(const float4*)(B + (size_t)(f >> 2) * ldb + k0 + ((f & 3) << 2));
            }
        } else {
#pragma unroll
            for (int r = 0; r < BR; r++) {
                int f = tid + r * 256;
                pb[r] = *(const float4*)(B + (size_t)(k0 + f / (BN / 4)) * ldb + ((f % (BN / 4)) << 2));
            }
        }
    };
    auto sstore = [&]() {
#pragma unroll
        for (int r = 0; r < 2; r++) {
            int f = tid + r * 256;
            int row = f >> 2, c4 = (f & 3) << 2;
            As[c4 + 0][row] = pa[r].x; As[c4 + 1][row] = pa[r].y;
            As[c4 + 2][row] = pa[r].z; As[c4 + 3][row] = pa[r].w;
        }
        if (BNT) {
#pragma unroll
            for (int r = 0; r < BR; r++) {
                int f = tid + r * 256;
                int row = f >> 2, c4 = (f & 3) << 2;
                Bs[c4 + 0][row] = pb[r].x; Bs[c4 + 1][row] = pb[r].y;
                Bs[c4 + 2][row] = pb[r].z; Bs[c4 + 3][row] = pb[r].w;
            }
        } else {
#pragma unroll
            for (int r = 0; r < BR; r++) {
                int f = tid + r * 256;
                *(float4*)&Bs[f / (BN / 4)][(f % (BN / 4)) << 2] = pb[r];
            }
        }
    };

    gload(0);
    sstore();
    __syncthreads();
    for (int k0 = 16; k0 <= K; k0 += 16) {
        if (k0 < K) gload(k0);      // prefetch next slab while computing current
#pragma unroll
        for (int kk = 0; kk < 16; kk++) {
            float4 a0 = *(const float4*)&As[kk][trow];
            float4 a1 = *(const float4*)&As[kk][trow + 4];
            unsigned long long bp[NP];
#pragma unroll
            for (int jp = 0; jp < NP; jp++)
                bp[jp] = *(const unsigned long long*)&Bs[kk][tcol + 2 * jp];
            float av[8] = {a0.x, a0.y, a0.z, a0.w, a1.x, a1.y, a1.z, a1.w};
#pragma unroll
            for (int i = 0; i < 8; i++) {
                unsigned long long ap = bcast2(av[i]);
#pragma unroll
                for (int jp = 0; jp < NP; jp++)
                    fma2(acc[i][jp], ap, bp[jp]);
            }
        }
        __syncthreads();
        if (k0 < K) { sstore(); __syncthreads(); }
    }
}

// ---------------- K1: BN (inference) + ReLU + (N,C,46)->(T,C) transpose ----------------
__global__ void __launch_bounds__(736) k_bnrelu(
    const float* __restrict__ ori, const float* __restrict__ gamma,
    const float* __restrict__ beta, const float* __restrict__ mean,
    const float* __restrict__ var)
{
    __shared__ float tile[16][NJ];
    int n = blockIdx.y, c0 = blockIdx.x * 16, tid = threadIdx.x;
    tile[tid / NJ][tid % NJ] = ori[((size_t)n * CC + c0 + tid / NJ) * NJ + tid % NJ];
    __syncthreads();
    int j2 = tid >> 4, c2 = tid & 15;
    int c = c0 + c2;
    float inv = gamma[c] * rsqrtf(var[c] + 1e-5f);
    float v = fmaf(tile[c2][j2], inv, beta[c] - mean[c] * inv);
    g_feat[((size_t)n * NJ + j2) * CC + c] = fmaxf(v, 0.0f);
}

// ---------------- K2: fused [theta|phi|g] projection, (T,512)x(768,512)^T ----------------
__global__ void __launch_bounds__(256) k_proj(
    const float* __restrict__ thw, const float* __restrict__ thb,
    const float* __restrict__ phw, const float* __restrict__ phb,
    const float* __restrict__ gw,  const float* __restrict__ gb)
{
    __shared__ __align__(16) float As[16][128];
    __shared__ __align__(16) float Bs[16][128];
    unsigned long long acc[8][4] = {};
    int tid = threadIdx.x;
    int m0 = blockIdx.y * 128;
    int sel = blockIdx.x >> 1;
    int prow0 = (blockIdx.x & 1) * 128;
    const float* Bp = (sel == 0) ? thw : (sel == 1 ? phw : gw);
    const float* bb = (sel == 0) ? thb : (sel == 1 ? phb : gb);
    gemm_tile_loop<128, true>(g_feat + (size_t)m0 * CC, CC,
                              Bp + (size_t)prow0 * CC, CC, CC, As, Bs, acc, tid);
    int trow = (tid >> 4) * 8, tcol = (tid & 15) * 8;
#pragma unroll
    for (int i = 0; i < 8; i++) {
        size_t m = m0 + trow + i;
#pragma unroll
        for (int jp = 0; jp < 4; jp++) {
            float2 f = unpk(acc[i][jp]);
            int nl = tcol + 2 * jp;
            float2 o = make_float2(f.x + bb[prow0 + nl], f.y + bb[prow0 + nl + 1]);
            *(float2*)&g_proj[m * 768 + blockIdx.x * 128 + nl] = o;
        }
    }
}

// ---------------- K3: attn logits = x_theta @ x_phi^T with block-diag mask ----------------
__global__ void __launch_bounds__(256) k_attn(float* __restrict__ attn)
{
    __shared__ __align__(16) float As[16][128];
    __shared__ __align__(16) float Bs[16][128];
    unsigned long long acc[8][4] = {};
    int tid = threadIdx.x;
    int m0 = blockIdx.y * 128, n0 = blockIdx.x * 128;
    gemm_tile_loop<128, true>(g_proj + (size_t)m0 * 768, 768,
                              g_proj + (size_t)n0 * 768 + 256, 768, 256, As, Bs, acc, tid);
    int trow = (tid >> 4) * 8, tcol = (tid & 15) * 8;
#pragma unroll
    for (int i = 0; i < 8; i++) {
        int m = m0 + trow + i;
        int bm = m / NJ;
#pragma unroll
        for (int jp = 0; jp < 4; jp++) {
            float2 f = unpk(acc[i][jp]);
            int n = n0 + tcol + 2 * jp;
            float2 o;
            o.x = (bm == n / NJ)       ? -1000.0f : f.x;
            o.y = (bm == (n + 1) / NJ) ? -1000.0f : f.y;
            *(float2*)&attn[(size_t)m * TT + n] = o;
        }
    }
}

// ---------------- K4: row softmax over 5888-wide rows, in place ----------------
__global__ void __launch_bounds__(256) k_softmax(float* __restrict__ attn)
{
    __shared__ float red[256];
    int t = threadIdx.x;
    float* p = attn + (size_t)blockIdx.x * TT;
    float v[23];
    float mx = -1e30f;
#pragma unroll
    for (int i = 0; i < 23; i++) { v[i] = p[t + 256 * i]; mx = fmaxf(mx, v[i]); }
    red[t] = mx; __syncthreads();
    for (int s = 128; s > 0; s >>= 1) { if (t < s) red[t] = fmaxf(red[t], red[t + s]); __syncthreads(); }
    mx = red[0]; __syncthreads();
    float sum = 0.0f;
#pragma unroll
    for (int i = 0; i < 23; i++) { v[i] = __expf(v[i] - mx); sum += v[i]; }
    red[t] = sum; __syncthreads();
    for (int s = 128; s > 0; s >>= 1) { if (t < s) red[t] += red[t + s]; __syncthreads(); }
    float inv = 1.0f / red[0];
#pragma unroll
    for (int i = 0; i < 23; i++) p[t + 256 * i] = v[i] * inv;
}

// ---------------- K5: y = P @ g_x, (T,T)x(T,256), NN ----------------
__global__ void __launch_bounds__(256) k_pv(const float* __restrict__ attn)
{
    __shared__ __align__(16) float As[16][128];
    __shared__ __align__(16) float Bs[16][64];
    unsigned long long acc[8][2] = {};
    int tid = threadIdx.x;
    int m0 = blockIdx.y * 128, n0 = blockIdx.x * 64;
    gemm_tile_loop<64, false>(attn + (size_t)m0 * TT, TT,
                              g_proj + 512 + n0, 768, TT, As, Bs, acc, tid);
    int trow = (tid >> 4) * 8, tcol = (tid & 15) * 4;
#pragma unroll
    for (int i = 0; i < 8; i++) {
        size_t m = m0 + trow + i;
#pragma unroll
        for (int jp = 0; jp < 2; jp++) {
            float2 f = unpk(acc[i][jp]);
            *(float2*)&g_y[m * CI + n0 + tcol + 2 * jp] = f;
        }
    }
}

// ---------------- K6: att_fea = y @ W_w^T + W_b + ori^T ----------------
__global__ void __launch_bounds__(256) k_out(
    const float* __restrict__ ori, const float* __restrict__ Ww,
    const float* __restrict__ Wb, float* __restrict__ out)
{
    __shared__ __align__(16) float As[16][128];
    __shared__ __align__(16) float Bs[16][128];
    unsigned long long acc[8][4] = {};
    int tid = threadIdx.x;
    int m0 = blockIdx.y * 128, n0 = blockIdx.x * 128;
    gemm_tile_loop<128, true>(g_y + (size_t)m0 * CI, CI,
                              Ww + (size_t)n0 * CI, CI, CI, As, Bs, acc, tid);
    int trow = (tid >> 4) * 8, tcol = (tid & 15) * 8;
#pragma unroll
    for (int i = 0; i < 8; i++) {
        int m = m0 + trow + i;
        int nb = m / NJ;
        int j = m - nb * NJ;
        const float* orow = ori + (size_t)nb * CC * NJ + j;
#pragma unroll
        for (int jp = 0; jp < 4; jp++) {
            float2 f = unpk(acc[i][jp]);
            int n = n0 + tcol + 2 * jp;
            float2 o;
            o.x = f.x + Wb[n]     + orow[(size_t)n * NJ];
            o.y = f.y + Wb[n + 1] + orow[(size_t)(n + 1) * NJ];
            *(float2*)&out[(size_t)m * CC + n] = o;
        }
    }
}

// ---------------- launch ----------------
extern "C" void kernel_launch(void* const* d_in, const int* in_sizes, int n_in,
                              void* d_out, int out_size)
{
    const float* ori = (const float*)d_in[0];
    const float* gm  = (const float*)d_in[1];
    const float* bt  = (const float*)d_in[2];
    const float* mn  = (const float*)d_in[3];
    const float* vr  = (const float*)d_in[4];
    const float* thw = (const float*)d_in[5];
    const float* thb = (const float*)d_in[6];
    const float* phw = (const float*)d_in[7];
    const float* phb = (const float*)d_in[8];
    const float* gw  = (const float*)d_in[9];
    const float* gb  = (const float*)d_in[10];
    const float* Ww  = (const float*)d_in[11];
    const float* Wb  = (const float*)d_in[12];

    float* out  = (float*)d_out;                       // att_fea (128,46,512)
    float* attn = out + (size_t)NBB * NJ * CC;         // f_div_C (5888,5888)

    k_bnrelu<<<dim3(32, 128), 736>>>(ori, gm, bt, mn, vr);
    k_proj  <<<dim3(6, 46),  256>>>(thw, thb, phw, phb, gw, gb);
    k_attn  <<<dim3(46, 46), 256>>>(attn);
    k_softmax<<<TT, 256>>>(attn);
    k_pv    <<<dim3(4, 46),  256>>>(attn);
    k_out   <<<dim3(4, 46),  256>>>(ori, Ww, Wb, out);
}

// round 7
// speedup vs baseline: 1.7096x; 1.7096x over previous
#include <cuda_runtime.h>
#include <cuda_bf16.h>
#include <cstdint>

typedef unsigned int u32;
typedef unsigned long long u64;
typedef __nv_bfloat16 bf16;

#define TT 5888
#define CC 512
#define CI 256
#define NJ 46

// ---------------- scratch (device globals; no allocation allowed) ----------------
__device__ __align__(16) bf16 g_fh[(size_t)TT * CC];   // feat hi
__device__ __align__(16) bf16 g_fl[(size_t)TT * CC];   // feat lo
__device__ __align__(16) bf16 g_w3h[768 * CC];         // [theta|phi|g] weights hi
__device__ __align__(16) bf16 g_w3l[768 * CC];         // lo
__device__ __align__(16) bf16 g_Wwb[CC * CI];          // W_w bf16
__device__ __align__(16) bf16 g_thh[(size_t)TT * CI];
__device__ __align__(16) bf16 g_thl[(size_t)TT * CI];
__device__ __align__(16) bf16 g_phh[(size_t)TT * CI];
__device__ __align__(16) bf16 g_phl[(size_t)TT * CI];
__device__ __align__(16) bf16 g_gxT[(size_t)CI * TT];  // g_x transposed [256, T]
__device__ __align__(16) bf16 g_yb[(size_t)TT * CI];   // y bf16

// ---------------- helpers ----------------
__device__ __forceinline__ u32 s2u(const void* p) {
    u32 a; asm("{ .reg .u64 t; cvta.to.shared.u64 t, %1; cvt.u32.u64 %0, t; }" : "=r"(a) : "l"(p));
    return a;
}
__device__ __forceinline__ u32 lds32(u32 a) {
    u32 v; asm volatile("ld.shared.b32 %0, [%1];" : "=r"(v) : "r"(a)); return v;
}
__device__ __forceinline__ u32 swz(u32 off) { return off ^ ((off >> 3) & 0x70); }

__device__ __forceinline__ void mma16816(float* c, const u32* a, const u32* b) {
    asm volatile(
        "mma.sync.aligned.m16n8k16.row.col.f32.bf16.bf16.f32 "
        "{%0,%1,%2,%3}, {%4,%5,%6,%7}, {%8,%9}, {%0,%1,%2,%3};"
        : "+f"(c[0]), "+f"(c[1]), "+f"(c[2]), "+f"(c[3])
        : "r"(a[0]), "r"(a[1]), "r"(a[2]), "r"(a[3]), "r"(b[0]), "r"(b[1]));
}

// load rows x 64 bf16 tile (row-major 128B rows, SW128) from global K-major [ld]
__device__ __forceinline__ void ldtile(u32 s, const bf16* __restrict__ g, size_t ld,
                                       int kc, int rows, int tid) {
    for (int f = tid; f < rows * 8; f += 256) {
        int r = f >> 3, c = (f & 7) << 3;
        uint4 v = *(const uint4*)(g + (size_t)r * ld + kc + c);
        u32 off = swz((r << 7) + (c << 1));
        asm volatile("st.shared.v4.b32 [%0], {%1,%2,%3,%4};" :: "r"(s + off),
                     "r"(v.x), "r"(v.y), "r"(v.z), "r"(v.w));
    }
}

// one warp-tile (64x32) pass over a 64-K smem chunk:
// A tile at sA (128 rows x 64 k, SW128), B tile at sB (128 rows x 64 k, SW128)
// acc[i][j][4]: i = m-subtile (16), j = n-subtile (8)
__device__ __forceinline__ void warp_pass(float (&acc)[4][4][4], u32 sA, u32 sB,
                                          int m0w, int n0w, int lane) {
    int lr = lane >> 2, lc = lane & 3;
#pragma unroll
    for (int kk = 0; kk < 4; kk++) {
        u32 kb = kk * 32 + lc * 4;
        u32 a[4][4], b[4][2];
#pragma unroll
        for (int i = 0; i < 4; i++) {
            u32 r0 = m0w + i * 16 + lr;
            u32 x = (r0 & 7) << 4;               // (r0+8)&7 == r0&7 here (r0%16 = lr < 8)
            u32 b0 = sA + r0 * 128, b1 = b0 + 8 * 128;
            a[i][0] = lds32(b0 + (kb ^ x));
            a[i][1] = lds32(b1 + (kb ^ x));
            a[i][2] = lds32(b0 + ((kb + 16) ^ x));
            a[i][3] = lds32(b1 + ((kb + 16) ^ x));
        }
#pragma unroll
        for (int j = 0; j < 4; j++) {
            u32 r0 = n0w + j * 8 + lr;
            u32 x = (r0 & 7) << 4;
            u32 bb = sB + r0 * 128;
            b[j][0] = lds32(bb + (kb ^ x));
            b[j][1] = lds32(bb + ((kb + 16) ^ x));
        }
#pragma unroll
        for (int i = 0; i < 4; i++)
#pragma unroll
            for (int j = 0; j < 4; j++)
                mma16816(acc[i][j], a[i], b[j]);
    }
}

// ---------------- K1: BN + ReLU + transpose -> feat hi/lo bf16 ----------------
__global__ void __launch_bounds__(736) k_bnrelu(
    const float* __restrict__ ori, const float* __restrict__ gamma,
    const float* __restrict__ beta, const float* __restrict__ mean,
    const float* __restrict__ var) {
    __shared__ float tile[16][NJ];
    int n = blockIdx.y, c0 = blockIdx.x * 16, tid = threadIdx.x;
    tile[tid / NJ][tid % NJ] = ori[((size_t)n * CC + c0 + tid / NJ) * NJ + tid % NJ];
    __syncthreads();
    int j2 = tid >> 4, c2 = tid & 15;
    int c = c0 + c2;
    float inv = gamma[c] * rsqrtf(var[c] + 1e-5f);
    float v = fmaxf(fmaf(tile[c2][j2], inv, beta[c] - mean[c] * inv), 0.0f);
    bf16 h = __float2bfloat16_rn(v);
    bf16 l = __float2bfloat16_rn(v - __bfloat162float(h));
    size_t o = ((size_t)n * NJ + j2) * CC + c;
    g_fh[o] = h; g_fl[o] = l;
}

// ---------------- K2: weight split -> bf16 ----------------
__global__ void __launch_bounds__(256) k_wsplit(
    const float* __restrict__ thw, const float* __restrict__ phw,
    const float* __restrict__ gw, const float* __restrict__ Ww) {
    int i = blockIdx.x * 256 + threadIdx.x;
    if (i < 768 * CC) {
        float v = (i < 131072) ? thw[i] : (i < 262144 ? phw[i - 131072] : gw[i - 262144]);
        bf16 h = __float2bfloat16_rn(v);
        g_w3h[i] = h;
        g_w3l[i] = __float2bfloat16_rn(v - __bfloat162float(h));
    } else {
        int j = i - 768 * CC;
        if (j < CC * CI) g_Wwb[j] = __float2bfloat16_rn(Ww[j]);
    }
}

// ---------------- K3: fused projections (3-pass split HMMA) ----------------
__global__ void __launch_bounds__(256, 2) k_proj(
    const float* __restrict__ thb, const float* __restrict__ phb, const float* __restrict__ gb) {
    extern __shared__ char smem[];
    u32 s0 = (s2u(smem) + 127) & ~127u;
    const u32 sAh = s0, sAl = s0 + 16384, sBh = s0 + 32768, sBl = s0 + 49152;
    int tid = threadIdx.x, wid = tid >> 5, lane = tid & 31;
    int m0w = (wid >> 2) * 64, n0w = (wid & 3) * 32;
    int lr = lane >> 2, lc = lane & 3;

    int sel = blockIdx.x >> 1, ph0 = (blockIdx.x & 1) * 128;
    size_t m0 = (size_t)blockIdx.y * 128;
    const bf16* Ah = g_fh + m0 * CC;
    const bf16* Al = g_fl + m0 * CC;
    const bf16* Bh = g_w3h + (size_t)(sel * 256 + ph0) * CC;
    const bf16* Bl = g_w3l + (size_t)(sel * 256 + ph0) * CC;

    float acc[4][4][4] = {};
    for (int c = 0; c < 8; c++) {
        int kc = c * 64;
        ldtile(sAh, Ah, CC, kc, 128, tid);
        ldtile(sAl, Al, CC, kc, 128, tid);
        ldtile(sBh, Bh, CC, kc, 128, tid);
        ldtile(sBl, Bl, CC, kc, 128, tid);
        __syncthreads();
        warp_pass(acc, sAh, sBh, m0w, n0w, lane);
        warp_pass(acc, sAh, sBl, m0w, n0w, lane);
        warp_pass(acc, sAl, sBh, m0w, n0w, lane);
        __syncthreads();
    }

    const float* bias = sel == 0 ? thb : (sel == 1 ? phb : gb);
#pragma unroll
    for (int i = 0; i < 4; i++)
#pragma unroll
        for (int j = 0; j < 4; j++) {
            int nl = n0w + j * 8 + 2 * lc;       // col in [0,128)
            int ng = ph0 + nl;                   // col in [0,256)
            float b0 = bias[ng], b1 = bias[ng + 1];
#pragma unroll
            for (int h = 0; h < 2; h++) {
                int m = (int)m0 + m0w + i * 16 + lr + 8 * h;
                float v0 = acc[i][j][2 * h] + b0;
                float v1 = acc[i][j][2 * h + 1] + b1;
                if (sel < 2) {
                    bf16* Dh = sel ? g_phh : g_thh;
                    bf16* Dl = sel ? g_phl : g_thl;
                    bf16 h0 = __float2bfloat16_rn(v0), h1 = __float2bfloat16_rn(v1);
                    bf16 l0 = __float2bfloat16_rn(v0 - __bfloat162float(h0));
                    bf16 l1 = __float2bfloat16_rn(v1 - __bfloat162float(h1));
                    __nv_bfloat162 hp; hp.x = h0; hp.y = h1;
                    __nv_bfloat162 lp; lp.x = l0; lp.y = l1;
                    *(u32*)&Dh[(size_t)m * CI + ng] = *(u32*)&hp;
                    *(u32*)&Dl[(size_t)m * CI + ng] = *(u32*)&lp;
                } else {
                    g_gxT[(size_t)ng * TT + m] = __float2bfloat16_rn(v0);
                    g_gxT[(size_t)(ng + 1) * TT + m] = __float2bfloat16_rn(v1);
                }
            }
        }
}

// ---------------- K4: attn logits (3-pass split HMMA) + mask ----------------
__global__ void __launch_bounds__(256, 2) k_attn(float* __restrict__ attn) {
    extern __shared__ char smem[];
    u32 s0 = (s2u(smem) + 127) & ~127u;
    const u32 sAh = s0, sAl = s0 + 16384, sBh = s0 + 32768, sBl = s0 + 49152;
    int tid = threadIdx.x, wid = tid >> 5, lane = tid & 31;
    int m0w = (wid >> 2) * 64, n0w = (wid & 3) * 32;
    int lr = lane >> 2, lc = lane & 3;

    size_t m0 = (size_t)blockIdx.y * 128;
    size_t n0 = (size_t)blockIdx.x * 128;

    float acc[4][4][4] = {};
    for (int c = 0; c < 4; c++) {
        int kc = c * 64;
        ldtile(sAh, g_thh + m0 * CI, CI, kc, 128, tid);
        ldtile(sAl, g_thl + m0 * CI, CI, kc, 128, tid);
        ldtile(sBh, g_phh + n0 * CI, CI, kc, 128, tid);
        ldtile(sBl, g_phl + n0 * CI, CI, kc, 128, tid);
        __syncthreads();
        warp_pass(acc, sAh, sBh, m0w, n0w, lane);
        warp_pass(acc, sAh, sBl, m0w, n0w, lane);
        warp_pass(acc, sAl, sBh, m0w, n0w, lane);
        __syncthreads();
    }

#pragma unroll
    for (int i = 0; i < 4; i++)
#pragma unroll
        for (int j = 0; j < 4; j++) {
            int n = (int)n0 + n0w + j * 8 + 2 * lc;
#pragma unroll
            for (int h = 0; h < 2; h++) {
                int m = (int)m0 + m0w + i * 16 + lr + 8 * h;
                int bm = m / NJ;
                float2 o;
                o.x = (n / NJ == bm)       ? -1000.0f : acc[i][j][2 * h];
                o.y = ((n + 1) / NJ == bm) ? -1000.0f : acc[i][j][2 * h + 1];
                *(float2*)&attn[(size_t)m * TT + n] = o;
            }
        }
}

// ---------------- K5: row softmax (in place) ----------------
__global__ void __launch_bounds__(256) k_softmax(float* __restrict__ attn) {
    __shared__ float red[256];
    int t = threadIdx.x;
    float* p = attn + (size_t)blockIdx.x * TT;
    float v[23];
    float mx = -1e30f;
#pragma unroll
    for (int i = 0; i < 23; i++) { v[i] = p[t + 256 * i]; mx = fmaxf(mx, v[i]); }
    red[t] = mx; __syncthreads();
    for (int s = 128; s > 0; s >>= 1) { if (t < s) red[t] = fmaxf(red[t], red[t + s]); __syncthreads(); }
    mx = red[0]; __syncthreads();
    float sum = 0.0f;
#pragma unroll
    for (int i = 0; i < 23; i++) { v[i] = __expf(v[i] - mx); sum += v[i]; }
    red[t] = sum; __syncthreads();
    for (int s = 128; s > 0; s >>= 1) { if (t < s) red[t] += red[t + s]; __syncthreads(); }
    float inv = 1.0f / red[0];
#pragma unroll
    for (int i = 0; i < 23; i++) p[t + 256 * i] = v[i] * inv;
}

// ---------------- K6: y = P @ g_x (single bf16 HMMA) ----------------
__global__ void __launch_bounds__(256, 2) k_pv(const float* __restrict__ attn) {
    extern __shared__ char smem[];
    u32 s0 = (s2u(smem) + 127) & ~127u;
    const u32 sA = s0, sB = s0 + 16384;
    int tid = threadIdx.x, wid = tid >> 5, lane = tid & 31;
    int m0w = (wid >> 2) * 64, n0w = (wid & 3) * 32;
    int lr = lane >> 2, lc = lane & 3;

    size_t m0 = (size_t)blockIdx.y * 128;
    size_t n0 = (size_t)blockIdx.x * 128;
    const float* P = attn + m0 * TT;

    float acc[4][4][4] = {};
    for (int c = 0; c < TT / 64; c++) {
        int kc = c * 64;
        // P chunk fp32 -> bf16 swizzled smem (128 x 64)
        for (int f = tid; f < 128 * 16; f += 256) {
            int r = f >> 4, c4 = (f & 15) << 2;
            float4 v = *(const float4*)(P + (size_t)r * TT + kc + c4);
            __nv_bfloat162 p0 = __floats2bfloat162_rn(v.x, v.y);
            __nv_bfloat162 p1 = __floats2bfloat162_rn(v.z, v.w);
            u32 off = swz((r << 7) + (c4 << 1));
            asm volatile("st.shared.v2.b32 [%0], {%1,%2};" :: "r"(sA + off),
                         "r"(*(u32*)&p0), "r"(*(u32*)&p1));
        }
        ldtile(sB, g_gxT + n0 * TT, TT, kc, 128, tid);
        __syncthreads();
        warp_pass(acc, sA, sB, m0w, n0w, lane);
        __syncthreads();
    }

#pragma unroll
    for (int i = 0; i < 4; i++)
#pragma unroll
        for (int j = 0; j < 4; j++) {
            int n = (int)n0 + n0w + j * 8 + 2 * lc;
#pragma unroll
            for (int h = 0; h < 2; h++) {
                int m = (int)m0 + m0w + i * 16 + lr + 8 * h;
                __nv_bfloat162 p = __floats2bfloat162_rn(acc[i][j][2 * h], acc[i][j][2 * h + 1]);
                *(u32*)&g_yb[(size_t)m * CI + n] = *(u32*)&p;
            }
        }
}

// ---------------- K7: out = y @ W_w^T + W_b + ori^T (single bf16 HMMA) ----------------
__global__ void __launch_bounds__(256, 2) k_out(
    const float* __restrict__ ori, const float* __restrict__ Wb, float* __restrict__ out) {
    extern __shared__ char smem[];
    u32 s0 = (s2u(smem) + 127) & ~127u;
    const u32 sA = s0, sB = s0 + 16384;
    int tid = threadIdx.x, wid = tid >> 5, lane = tid & 31;
    int m0w = (wid >> 2) * 64, n0w = (wid & 3) * 32;
    int lr = lane >> 2, lc = lane & 3;

    size_t m0 = (size_t)blockIdx.y * 128;
    size_t n0 = (size_t)blockIdx.x * 128;

    float acc[4][4][4] = {};
    for (int c = 0; c < 4; c++) {
        int kc = c * 64;
        ldtile(sA, g_yb + m0 * CI, CI, kc, 128, tid);
        ldtile(sB, g_Wwb + n0 * CI, CI, kc, 128, tid);
        __syncthreads();
        warp_pass(acc, sA, sB, m0w, n0w, lane);
        __syncthreads();
    }

#pragma unroll
    for (int i = 0; i < 4; i++)
#pragma unroll
        for (int j = 0; j < 4; j++) {
            int n = (int)n0 + n0w + j * 8 + 2 * lc;
            float b0 = Wb[n], b1 = Wb[n + 1];
#pragma unroll
            for (int h = 0; h < 2; h++) {
                int m = (int)m0 + m0w + i * 16 + lr + 8 * h;
                int nb = m / NJ, jj = m - nb * NJ;
                const float* orow = ori + (size_t)nb * CC * NJ + jj;
                float2 o;
                o.x = acc[i][j][2 * h]     + b0 + orow[(size_t)n * NJ];
                o.y = acc[i][j][2 * h + 1] + b1 + orow[(size_t)(n + 1) * NJ];
                *(float2*)&out[(size_t)m * CC + n] = o;
            }
        }
}

// ---------------- launch ----------------
extern "C" void kernel_launch(void* const* d_in, const int* in_sizes, int n_in,
                              void* d_out, int out_size) {
    const float* ori = (const float*)d_in[0];
    const float* gm  = (const float*)d_in[1];
    const float* bt  = (const float*)d_in[2];
    const float* mn  = (const float*)d_in[3];
    const float* vr  = (const float*)d_in[4];
    const float* thw = (const float*)d_in[5];
    const float* thb = (const float*)d_in[6];
    const float* phw = (const float*)d_in[7];
    const float* phb = (const float*)d_in[8];
    const float* gw  = (const float*)d_in[9];
    const float* gb  = (const float*)d_in[10];
    const float* Ww  = (const float*)d_in[11];
    const float* Wb  = (const float*)d_in[12];

    float* out  = (float*)d_out;
    float* attn = out + (size_t)128 * NJ * CC;

    cudaFuncSetAttribute(k_proj, cudaFuncAttributeMaxDynamicSharedMemorySize, 65792);
    cudaFuncSetAttribute(k_attn, cudaFuncAttributeMaxDynamicSharedMemorySize, 65792);

    k_bnrelu<<<dim3(32, 128), 736>>>(ori, gm, bt, mn, vr);
    k_wsplit<<<2048, 256>>>(thw, phw, gw, Ww);
    k_proj<<<dim3(6, 46), 256, 65792>>>(thb, phb, gb);
    k_attn<<<dim3(46, 46), 256, 65792>>>(attn);
    k_softmax<<<TT, 256>>>(attn);
    k_pv<<<dim3(2, 46), 256, 33024>>>(attn);
    k_out<<<dim3(4, 46), 256, 33024>>>(ori, Wb, out);
}

// round 12
// speedup vs baseline: 1.8949x; 1.1084x over previous
#include <cuda_runtime.h>
#include <cuda_bf16.h>
#include <cstdint>

typedef unsigned int u32;
typedef unsigned long long u64;
typedef __nv_bfloat16 bf16;

#define TT 5888
#define CC 512
#define CI 256
#define NJ 46

// ---------------- scratch (device globals; no allocation allowed) ----------------
__device__ __align__(16) bf16 g_fh[(size_t)TT * CC];   // feat hi
__device__ __align__(16) bf16 g_fl[(size_t)TT * CC];   // feat lo
__device__ __align__(16) bf16 g_w3h[768 * CC];         // [theta|phi|g] weights hi
__device__ __align__(16) bf16 g_w3l[768 * CC];         // lo
__device__ __align__(16) bf16 g_Wwb[CC * CI];          // W_w bf16
__device__ __align__(16) bf16 g_thh[(size_t)TT * CI];
__device__ __align__(16) bf16 g_thl[(size_t)TT * CI];
__device__ __align__(16) bf16 g_phh[(size_t)TT * CI];
__device__ __align__(16) bf16 g_phl[(size_t)TT * CI];
__device__ __align__(16) bf16 g_gxT[(size_t)CI * TT];  // g_x transposed [256, T]
__device__ __align__(16) bf16 g_yb[(size_t)TT * CI];   // y bf16
__device__ __align__(16) bf16 g_pb[(size_t)TT * TT];   // f_div_C bf16 copy

// ---------------- helpers ----------------
__device__ __forceinline__ u32 s2u(const void* p) {
    u32 a; asm("{ .reg .u64 t; cvta.to.shared.u64 t, %1; cvt.u32.u64 %0, t; }" : "=r"(a) : "l"(p));
    return a;
}
__device__ __forceinline__ u32 swz(u32 off) { return off ^ ((off >> 3) & 0x70); }

__device__ __forceinline__ void mma16816(float* c, const u32* a, const u32* b) {
    asm volatile(
        "mma.sync.aligned.m16n8k16.row.col.f32.bf16.bf16.f32 "
        "{%0,%1,%2,%3}, {%4,%5,%6,%7}, {%8,%9}, {%0,%1,%2,%3};"
        : "+f"(c[0]), "+f"(c[1]), "+f"(c[2]), "+f"(c[3])
        : "r"(a[0]), "r"(a[1]), "r"(a[2]), "r"(a[3]), "r"(b[0]), "r"(b[1]));
}
__device__ __forceinline__ void ldsm4(u32& r0, u32& r1, u32& r2, u32& r3, u32 addr) {
    asm volatile("ldmatrix.sync.aligned.m8n8.x4.shared.b16 {%0,%1,%2,%3}, [%4];"
        : "=r"(r0), "=r"(r1), "=r"(r2), "=r"(r3) : "r"(addr));
}

// load rows x 64 bf16 tile (row-major 128B rows, SW128) from global K-major [ld]
__device__ __forceinline__ void ldtile(u32 s, const bf16* __restrict__ g, size_t ld,
                                       int kc, int rows, int tid) {
    for (int f = tid; f < rows * 8; f += 256) {
        int r = f >> 3, c = (f & 7) << 3;
        uint4 v = *(const uint4*)(g + (size_t)r * ld + kc + c);
        u32 off = swz((r << 7) + (c << 1));
        asm volatile("st.shared.v4.b32 [%0], {%1,%2,%3,%4};" :: "r"(s + off),
                     "r"(v.x), "r"(v.y), "r"(v.z), "r"(v.w));
    }
}

// one warp-tile (MI*16 x 32) pass over a 64-K smem chunk via ldmatrix.
// A at sA (rows x 64k SW128), B at sB (128 rows x 64k SW128).
template<int MI>
__device__ __forceinline__ void warp_pass(float (&acc)[MI][4][4], u32 sA, u32 sB,
                                          int m0w, int n0w, int lane) {
    u32 mask = (lane & 7) << 4;
    u32 asub = (lane >> 4) << 4;             // 0 / 16 bytes (col half)
    u32 bsub = ((lane >> 3) & 1) << 4;       // 0 / 16 bytes (k half)
    u32 aBase[MI], bBase[2];
#pragma unroll
    for (int i = 0; i < MI; i++)
        aBase[i] = sA + (u32)(m0w + i * 16 + (lane & 15)) * 128;
#pragma unroll
    for (int jp = 0; jp < 2; jp++)
        bBase[jp] = sB + (u32)(n0w + jp * 16 + ((lane >> 4) << 3) + (lane & 7)) * 128;
#pragma unroll
    for (int kk = 0; kk < 4; kk++) {
        u32 a[MI][4], b[4][2];
#pragma unroll
        for (int i = 0; i < MI; i++)
            ldsm4(a[i][0], a[i][1], a[i][2], a[i][3], aBase[i] + (((u32)kk * 32 + asub) ^ mask));
#pragma unroll
        for (int jp = 0; jp < 2; jp++) {
            u32 r0, r1, r2, r3;
            ldsm4(r0, r1, r2, r3, bBase[jp] + (((u32)kk * 32 + bsub) ^ mask));
            b[2 * jp][0] = r0; b[2 * jp][1] = r1;
            b[2 * jp + 1][0] = r2; b[2 * jp + 1][1] = r3;
        }
#pragma unroll
        for (int i = 0; i < MI; i++)
#pragma unroll
            for (int j = 0; j < 4; j++)
                mma16816(acc[i][j], a[i], b[j]);
    }
}

// ---------------- K1: BN + ReLU + transpose -> feat hi/lo bf16 ----------------
__global__ void __launch_bounds__(736) k_bnrelu(
    const float* __restrict__ ori, const float* __restrict__ gamma,
    const float* __restrict__ beta, const float* __restrict__ mean,
    const float* __restrict__ var) {
    __shared__ float tile[16][NJ];
    int n = blockIdx.y, c0 = blockIdx.x * 16, tid = threadIdx.x;
    tile[tid / NJ][tid % NJ] = ori[((size_t)n * CC + c0 + tid / NJ) * NJ + tid % NJ];
    __syncthreads();
    int j2 = tid >> 4, c2 = tid & 15;
    int c = c0 + c2;
    float inv = gamma[c] * rsqrtf(var[c] + 1e-5f);
    float v = fmaxf(fmaf(tile[c2][j2], inv, beta[c] - mean[c] * inv), 0.0f);
    bf16 h = __float2bfloat16_rn(v);
    bf16 l = __float2bfloat16_rn(v - __bfloat162float(h));
    size_t o = ((size_t)n * NJ + j2) * CC + c;
    g_fh[o] = h; g_fl[o] = l;
}

// ---------------- K2: weight split -> bf16 ----------------
__global__ void __launch_bounds__(256) k_wsplit(
    const float* __restrict__ thw, const float* __restrict__ phw,
    const float* __restrict__ gw, const float* __restrict__ Ww) {
    int i = blockIdx.x * 256 + threadIdx.x;
    if (i < 768 * CC) {
        float v = (i < 131072) ? thw[i] : (i < 262144 ? phw[i - 131072] : gw[i - 262144]);
        bf16 h = __float2bfloat16_rn(v);
        g_w3h[i] = h;
        g_w3l[i] = __float2bfloat16_rn(v - __bfloat162float(h));
    } else {
        int j = i - 768 * CC;
        if (j < CC * CI) g_Wwb[j] = __float2bfloat16_rn(Ww[j]);
    }
}

// ---------------- K3: fused projections (3-pass split HMMA) ----------------
__global__ void __launch_bounds__(256, 2) k_proj(
    const float* __restrict__ thb, const float* __restrict__ phb, const float* __restrict__ gb) {
    extern __shared__ char smem[];
    u32 s0 = (s2u(smem) + 127) & ~127u;
    const u32 sAh = s0, sAl = s0 + 16384, sBh = s0 + 32768, sBl = s0 + 49152;
    int tid = threadIdx.x, wid = tid >> 5, lane = tid & 31;
    int m0w = (wid >> 2) * 64, n0w = (wid & 3) * 32;
    int lr = lane >> 2, lc = lane & 3;

    int sel = blockIdx.x >> 1, ph0 = (blockIdx.x & 1) * 128;
    size_t m0 = (size_t)blockIdx.y * 128;
    const bf16* Ah = g_fh + m0 * CC;
    const bf16* Al = g_fl + m0 * CC;
    const bf16* Bh = g_w3h + (size_t)(sel * 256 + ph0) * CC;
    const bf16* Bl = g_w3l + (size_t)(sel * 256 + ph0) * CC;

    float acc[4][4][4] = {};
    for (int c = 0; c < 8; c++) {
        int kc = c * 64;
        ldtile(sAh, Ah, CC, kc, 128, tid);
        ldtile(sAl, Al, CC, kc, 128, tid);
        ldtile(sBh, Bh, CC, kc, 128, tid);
        ldtile(sBl, Bl, CC, kc, 128, tid);
        __syncthreads();
        warp_pass<4>(acc, sAh, sBh, m0w, n0w, lane);
        warp_pass<4>(acc, sAh, sBl, m0w, n0w, lane);
        warp_pass<4>(acc, sAl, sBh, m0w, n0w, lane);
        __syncthreads();
    }

    const float* bias = sel == 0 ? thb : (sel == 1 ? phb : gb);
#pragma unroll
    for (int i = 0; i < 4; i++)
#pragma unroll
        for (int j = 0; j < 4; j++) {
            int nl = n0w + j * 8 + 2 * lc;       // col in [0,128)
            int ng = ph0 + nl;                   // col in [0,256)
            float b0 = bias[ng], b1 = bias[ng + 1];
#pragma unroll
            for (int h = 0; h < 2; h++) {
                int m = (int)m0 + m0w + i * 16 + lr + 8 * h;
                float v0 = acc[i][j][2 * h] + b0;
                float v1 = acc[i][j][2 * h + 1] + b1;
                if (sel < 2) {
                    bf16* Dh = sel ? g_phh : g_thh;
                    bf16* Dl = sel ? g_phl : g_thl;
                    bf16 h0 = __float2bfloat16_rn(v0), h1 = __float2bfloat16_rn(v1);
                    bf16 l0 = __float2bfloat16_rn(v0 - __bfloat162float(h0));
                    bf16 l1 = __float2bfloat16_rn(v1 - __bfloat162float(h1));
                    __nv_bfloat162 hp; hp.x = h0; hp.y = h1;
                    __nv_bfloat162 lp; lp.x = l0; lp.y = l1;
                    *(u32*)&Dh[(size_t)m * CI + ng] = *(u32*)&hp;
                    *(u32*)&Dl[(size_t)m * CI + ng] = *(u32*)&lp;
                } else {
                    g_gxT[(size_t)ng * TT + m] = __float2bfloat16_rn(v0);
                    g_gxT[(size_t)(ng + 1) * TT + m] = __float2bfloat16_rn(v1);
                }
            }
        }
}

// ---------------- K4: attn logits (3-pass split HMMA) + mask ----------------
__global__ void __launch_bounds__(256, 2) k_attn(float* __restrict__ attn) {
    extern __shared__ char smem[];
    u32 s0 = (s2u(smem) + 127) & ~127u;
    const u32 sAh = s0, sAl = s0 + 16384, sBh = s0 + 32768, sBl = s0 + 49152;
    int tid = threadIdx.x, wid = tid >> 5, lane = tid & 31;
    int m0w = (wid >> 2) * 64, n0w = (wid & 3) * 32;
    int lr = lane >> 2, lc = lane & 3;

    size_t m0 = (size_t)blockIdx.y * 128;
    size_t n0 = (size_t)blockIdx.x * 128;

    float acc[4][4][4] = {};
    for (int c = 0; c < 4; c++) {
        int kc = c * 64;
        ldtile(sAh, g_thh + m0 * CI, CI, kc, 128, tid);
        ldtile(sAl, g_thl + m0 * CI, CI, kc, 128, tid);
        ldtile(sBh, g_phh + n0 * CI, CI, kc, 128, tid);
        ldtile(sBl, g_phl + n0 * CI, CI, kc, 128, tid);
        __syncthreads();
        warp_pass<4>(acc, sAh, sBh, m0w, n0w, lane);
        warp_pass<4>(acc, sAh, sBl, m0w, n0w, lane);
        warp_pass<4>(acc, sAl, sBh, m0w, n0w, lane);
        __syncthreads();
    }

#pragma unroll
    for (int i = 0; i < 4; i++)
#pragma unroll
        for (int j = 0; j < 4; j++) {
            int n = (int)n0 + n0w + j * 8 + 2 * lc;
#pragma unroll
            for (int h = 0; h < 2; h++) {
                int m = (int)m0 + m0w + i * 16 + lr + 8 * h;
                int bm = m / NJ;
                float2 o;
                o.x = (n / NJ == bm)       ? -1000.0f : acc[i][j][2 * h];
                o.y = ((n + 1) / NJ == bm) ? -1000.0f : acc[i][j][2 * h + 1];
                *(float2*)&attn[(size_t)m * TT + n] = o;
            }
        }
}

// ---------------- K5: row softmax (in place) + bf16 copy ----------------
__global__ void __launch_bounds__(256) k_softmax(float* __restrict__ attn) {
    __shared__ float red[256];
    int t = threadIdx.x;
    float* p = attn + (size_t)blockIdx.x * TT;
    bf16* pb = g_pb + (size_t)blockIdx.x * TT;
    float v[23];
    float mx = -1e30f;
#pragma unroll
    for (int i = 0; i < 23; i++) { v[i] = p[t + 256 * i]; mx = fmaxf(mx, v[i]); }
    red[t] = mx; __syncthreads();
    for (int s = 128; s > 0; s >>= 1) { if (t < s) red[t] = fmaxf(red[t], red[t + s]); __syncthreads(); }
    mx = red[0]; __syncthreads();
    float sum = 0.0f;
#pragma unroll
    for (int i = 0; i < 23; i++) { v[i] = __expf(v[i] - mx); sum += v[i]; }
    red[t] = sum; __syncthreads();
    for (int s = 128; s > 0; s >>= 1) { if (t < s) red[t] += red[t + s]; __syncthreads(); }
    float inv = 1.0f / red[0];
#pragma unroll
    for (int i = 0; i < 23; i++) {
        float r = v[i] * inv;
        p[t + 256 * i] = r;
        pb[t + 256 * i] = __float2bfloat16_rn(r);
    }
}

// ---------------- K6: y = P @ g_x (bf16 HMMA, M=64 tiles) ----------------
__global__ void __launch_bounds__(256) k_pv() {
    extern __shared__ char smem[];
    u32 s0 = (s2u(smem) + 127) & ~127u;
    const u32 sA = s0, sB = s0 + 8192;
    int tid = threadIdx.x, wid = tid >> 5, lane = tid & 31;
    int m0w = (wid >> 2) * 32, n0w = (wid & 3) * 32;
    int lr = lane >> 2, lc = lane & 3;

    size_t m0 = (size_t)blockIdx.y * 64;
    size_t n0 = (size_t)blockIdx.x * 128;

    float acc[2][4][4] = {};
    for (int c = 0; c < TT / 64; c++) {
        int kc = c * 64;
        ldtile(sA, g_pb + m0 * TT, TT, kc, 64, tid);
        ldtile(sB, g_gxT + n0 * TT, TT, kc, 128, tid);
        __syncthreads();
        warp_pass<2>(acc, sA, sB, m0w, n0w, lane);
        __syncthreads();
    }

#pragma unroll
    for (int i = 0; i < 2; i++)
#pragma unroll
        for (int j = 0; j < 4; j++) {
            int n = (int)n0 + n0w + j * 8 + 2 * lc;
#pragma unroll
            for (int h = 0; h < 2; h++) {
                int m = (int)m0 + m0w + i * 16 + lr + 8 * h;
                __nv_bfloat162 p = __floats2bfloat162_rn(acc[i][j][2 * h], acc[i][j][2 * h + 1]);
                *(u32*)&g_yb[(size_t)m * CI + n] = *(u32*)&p;
            }
        }
}

// ---------------- K7: out = y @ W_w^T + W_b + ori^T (bf16 HMMA) ----------------
__global__ void __launch_bounds__(256, 2) k_out(
    const float* __restrict__ ori, const float* __restrict__ Wb, float* __restrict__ out) {
    extern __shared__ char smem[];
    u32 s0 = (s2u(smem) + 127) & ~127u;
    const u32 sA = s0, sB = s0 + 16384;
    int tid = threadIdx.x, wid = tid >> 5, lane = tid & 31;
    int m0w = (wid >> 2) * 64, n0w = (wid & 3) * 32;
    int lr = lane >> 2, lc = lane & 3;

    size_t m0 = (size_t)blockIdx.y * 128;
    size_t n0 = (size_t)blockIdx.x * 128;

    float acc[4][4][4] = {};
    for (int c = 0; c < 4; c++) {
        int kc = c * 64;
        ldtile(sA, g_yb + m0 * CI, CI, kc, 128, tid);
        ldtile(sB, g_Wwb + n0 * CI, CI, kc, 128, tid);
        __syncthreads();
        warp_pass<4>(acc, sA, sB, m0w, n0w, lane);
        __syncthreads();
    }

#pragma unroll
    for (int i = 0; i < 4; i++)
#pragma unroll
        for (int j = 0; j < 4; j++) {
            int n = (int)n0 + n0w + j * 8 + 2 * lc;
            float b0 = Wb[n], b1 = Wb[n + 1];
#pragma unroll
            for (int h = 0; h < 2; h++) {
                int m = (int)m0 + m0w + i * 16 + lr + 8 * h;
                int nb = m / NJ, jj = m - nb * NJ;
                const float* orow = ori + (size_t)nb * CC * NJ + jj;
                float2 o;
                o.x = acc[i][j][2 * h]     + b0 + orow[(size_t)n * NJ];
                o.y = acc[i][j][2 * h + 1] + b1 + orow[(size_t)(n + 1) * NJ];
                *(float2*)&out[(size_t)m * CC + n] = o;
            }
        }
}

// ---------------- launch ----------------
extern "C" void kernel_launch(void* const* d_in, const int* in_sizes, int n_in,
                              void* d_out, int out_size) {
    const float* ori = (const float*)d_in[0];
    const float* gm  = (const float*)d_in[1];
    const float* bt  = (const float*)d_in[2];
    const float* mn  = (const float*)d_in[3];
    const float* vr  = (const float*)d_in[4];
    const float* thw = (const float*)d_in[5];
    const float* thb = (const float*)d_in[6];
    const float* phw = (const float*)d_in[7];
    const float* phb = (const float*)d_in[8];
    const float* gw  = (const float*)d_in[9];
    const float* gb  = (const float*)d_in[10];
    const float* Ww  = (const float*)d_in[11];
    const float* Wb  = (const float*)d_in[12];

    float* out  = (float*)d_out;
    float* attn = out + (size_t)128 * NJ * CC;

    cudaFuncSetAttribute(k_proj, cudaFuncAttributeMaxDynamicSharedMemorySize, 65792);
    cudaFuncSetAttribute(k_attn, cudaFuncAttributeMaxDynamicSharedMemorySize, 65792);

    k_bnrelu<<<dim3(32, 128), 736>>>(ori, gm, bt, mn, vr);
    k_wsplit<<<2048, 256>>>(thw, phw, gw, Ww);
    k_proj<<<dim3(6, 46), 256, 65792>>>(thb, phb, gb);
    k_attn<<<dim3(46, 46), 256, 65792>>>(attn);
    k_softmax<<<TT, 256>>>(attn);
    k_pv<<<dim3(2, 92), 256, 24704>>>();
    k_out<<<dim3(4, 46), 256, 33024>>>(ori, Wb, out);
}

// round 15
// speedup vs baseline: 3.7249x; 1.9657x over previous
#include <cuda_runtime.h>
#include <cuda_bf16.h>
#include <cstdint>

typedef unsigned int u32;
typedef unsigned long long u64;
typedef __nv_bfloat16 bf16;

#define TT 5888
#define CC 512
#define CI 256
#define NJ 46

// ---------------- scratch (device globals; no allocation allowed) ----------------
__device__ __align__(16) bf16 g_fh[(size_t)TT * CC];
__device__ __align__(16) bf16 g_fl[(size_t)TT * CC];
__device__ __align__(16) bf16 g_w3h[768 * CC];
__device__ __align__(16) bf16 g_w3l[768 * CC];
__device__ __align__(16) bf16 g_Wwb[CC * CI];
__device__ __align__(16) bf16 g_thh[(size_t)TT * CI];
__device__ __align__(16) bf16 g_thl[(size_t)TT * CI];
__device__ __align__(16) bf16 g_phh[(size_t)TT * CI];
__device__ __align__(16) bf16 g_phl[(size_t)TT * CI];
__device__ __align__(16) bf16 g_gxT[(size_t)CI * TT];
__device__ __align__(16) bf16 g_yb[(size_t)TT * CI];
__device__ __align__(16) bf16 g_pb[(size_t)TT * TT];

// ---------------- helpers ----------------
__device__ __forceinline__ u32 s2u(const void* p) {
    u32 a; asm("{ .reg .u64 t; cvta.to.shared.u64 t, %1; cvt.u32.u64 %0, t; }" : "=r"(a) : "l"(p));
    return a;
}
__device__ __forceinline__ u32 swz(u32 off) { return off ^ ((off >> 3) & 0x70); }

__device__ __forceinline__ void mma16816(float* c, const u32* a, const u32* b) {
    asm volatile(
        "mma.sync.aligned.m16n8k16.row.col.f32.bf16.bf16.f32 "
        "{%0,%1,%2,%3}, {%4,%5,%6,%7}, {%8,%9}, {%0,%1,%2,%3};"
        : "+f"(c[0]), "+f"(c[1]), "+f"(c[2]), "+f"(c[3])
        : "r"(a[0]), "r"(a[1]), "r"(a[2]), "r"(a[3]), "r"(b[0]), "r"(b[1]));
}
__device__ __forceinline__ void ldsm4(u32& r0, u32& r1, u32& r2, u32& r3, u32 addr) {
    asm volatile("ldmatrix.sync.aligned.m8n8.x4.shared.b16 {%0,%1,%2,%3}, [%4];"
        : "=r"(r0), "=r"(r1), "=r"(r2), "=r"(r3) : "r"(addr));
}
#define CP_COMMIT() asm volatile("cp.async.commit_group;" ::: "memory")
#define CP_WAIT1()  asm volatile("cp.async.wait_group 1;" ::: "memory")
#define CP_WAIT0()  asm volatile("cp.async.wait_group 0;" ::: "memory")

// async load rows x 64 bf16 tile (128B rows, SW128) from global K-major [ld]
__device__ __forceinline__ void ldtile_async(u32 s, const bf16* __restrict__ g, size_t ld,
                                             int kc, int rows, int tid, int nt) {
    for (int f = tid; f < rows * 8; f += nt) {
        int r = f >> 3, c = (f & 7) << 3;
        const bf16* src = g + (size_t)r * ld + kc + c;
        u32 dst = s + swz((r << 7) + (c << 1));
        asm volatile("cp.async.cg.shared.global [%0], [%1], 16;" :: "r"(dst), "l"(src));
    }
}
// sync version (k_out)
__device__ __forceinline__ void ldtile(u32 s, const bf16* __restrict__ g, size_t ld,
                                       int kc, int rows, int tid) {
    for (int f = tid; f < rows * 8; f += 256) {
        int r = f >> 3, c = (f & 7) << 3;
        uint4 v = *(const uint4*)(g + (size_t)r * ld + kc + c);
        u32 off = swz((r << 7) + (c << 1));
        asm volatile("st.shared.v4.b32 [%0], {%1,%2,%3,%4};" :: "r"(s + off),
                     "r"(v.x), "r"(v.y), "r"(v.z), "r"(v.w));
    }
}

// single-pass warp tile (MI*16 x 32) over a 64-K chunk (k_pv / k_out)
template<int MI>
__device__ __forceinline__ void warp_pass(float (&acc)[MI][4][4], u32 sA, u32 sB,
                                          int m0w, int n0w, int lane) {
    u32 mask = (lane & 7) << 4;
    u32 asub = (lane >> 4) << 4;
    u32 bsub = ((lane >> 3) & 1) << 4;
    u32 aBase[MI], bBase[2];
#pragma unroll
    for (int i = 0; i < MI; i++)
        aBase[i] = sA + (u32)(m0w + i * 16 + (lane & 15)) * 128;
#pragma unroll
    for (int jp = 0; jp < 2; jp++)
        bBase[jp] = sB + (u32)(n0w + jp * 16 + ((lane >> 4) << 3) + (lane & 7)) * 128;
#pragma unroll
    for (int kk = 0; kk < 4; kk++) {
        u32 a[MI][4], b[4][2];
#pragma unroll
        for (int i = 0; i < MI; i++)
            ldsm4(a[i][0], a[i][1], a[i][2], a[i][3], aBase[i] + (((u32)kk * 32 + asub) ^ mask));
#pragma unroll
        for (int jp = 0; jp < 2; jp++) {
            u32 r0, r1, r2, r3;
            ldsm4(r0, r1, r2, r3, bBase[jp] + (((u32)kk * 32 + bsub) ^ mask));
            b[2 * jp][0] = r0; b[2 * jp][1] = r1;
            b[2 * jp + 1][0] = r2; b[2 * jp + 1][1] = r3;
        }
#pragma unroll
        for (int i = 0; i < MI; i++)
#pragma unroll
            for (int j = 0; j < 4; j++)
                mma16816(acc[i][j], a[i], b[j]);
    }
}

// fused 3-pass split warp tile (64 x 32): Ah*Bh + Ah*Bl + Al*Bh
__device__ __forceinline__ void warp_pass3(float (&acc)[4][4][4], u32 sAh, u32 sAl,
                                           u32 sBh, u32 sBl, int m0w, int n0w, int lane) {
    u32 mask = (lane & 7) << 4;
    u32 asub = (lane >> 4) << 4;
    u32 bsub = ((lane >> 3) & 1) << 4;
    u32 aoff[4], boff[2];
#pragma unroll
    for (int i = 0; i < 4; i++)
        aoff[i] = (u32)(m0w + i * 16 + (lane & 15)) * 128;
#pragma unroll
    for (int jp = 0; jp < 2; jp++)
        boff[jp] = (u32)(n0w + jp * 16 + ((lane >> 4) << 3) + (lane & 7)) * 128;
#pragma unroll
    for (int kk = 0; kk < 4; kk++) {
        u32 ka = ((u32)kk * 32 + asub) ^ mask;
        u32 kb = ((u32)kk * 32 + bsub) ^ mask;
        u32 ah[4][4], bh[4][2];
#pragma unroll
        for (int i = 0; i < 4; i++)
            ldsm4(ah[i][0], ah[i][1], ah[i][2], ah[i][3], sAh + aoff[i] + ka);
#pragma unroll
        for (int jp = 0; jp < 2; jp++) {
            u32 r0, r1, r2, r3;
            ldsm4(r0, r1, r2, r3, sBh + boff[jp] + kb);
            bh[2 * jp][0] = r0; bh[2 * jp][1] = r1;
            bh[2 * jp + 1][0] = r2; bh[2 * jp + 1][1] = r3;
        }
#pragma unroll
        for (int i = 0; i < 4; i++)
#pragma unroll
            for (int j = 0; j < 4; j++)
                mma16816(acc[i][j], ah[i], bh[j]);
        {   // Ah x Bl
            u32 bl[4][2];
#pragma unroll
            for (int jp = 0; jp < 2; jp++) {
                u32 r0, r1, r2, r3;
                ldsm4(r0, r1, r2, r3, sBl + boff[jp] + kb);
                bl[2 * jp][0] = r0; bl[2 * jp][1] = r1;
                bl[2 * jp + 1][0] = r2; bl[2 * jp + 1][1] = r3;
            }
#pragma unroll
            for (int i = 0; i < 4; i++)
#pragma unroll
                for (int j = 0; j < 4; j++)
                    mma16816(acc[i][j], ah[i], bl[j]);
        }
        {   // Al x Bh
            u32 al[4][4];
#pragma unroll
            for (int i = 0; i < 4; i++)
                ldsm4(al[i][0], al[i][1], al[i][2], al[i][3], sAl + aoff[i] + ka);
#pragma unroll
            for (int i = 0; i < 4; i++)
#pragma unroll
                for (int j = 0; j < 4; j++)
                    mma16816(acc[i][j], al[i], bh[j]);
        }
    }
}

// ---------------- K1: BN + ReLU + transpose -> feat hi/lo bf16 ----------------
__global__ void __launch_bounds__(736) k_bnrelu(
    const float* __restrict__ ori, const float* __restrict__ gamma,
    const float* __restrict__ beta, const float* __restrict__ mean,
    const float* __restrict__ var) {
    __shared__ float tile[16][NJ];
    int n = blockIdx.y, c0 = blockIdx.x * 16, tid = threadIdx.x;
    tile[tid / NJ][tid % NJ] = ori[((size_t)n * CC + c0 + tid / NJ) * NJ + tid % NJ];
    __syncthreads();
    int j2 = tid >> 4, c2 = tid & 15;
    int c = c0 + c2;
    float inv = gamma[c] * rsqrtf(var[c] + 1e-5f);
    float v = fmaxf(fmaf(tile[c2][j2], inv, beta[c] - mean[c] * inv), 0.0f);
    bf16 h = __float2bfloat16_rn(v);
    bf16 l = __float2bfloat16_rn(v - __bfloat162float(h));
    size_t o = ((size_t)n * NJ + j2) * CC + c;
    g_fh[o] = h; g_fl[o] = l;
}

// ---------------- K2: weight split -> bf16 ----------------
__global__ void __launch_bounds__(256) k_wsplit(
    const float* __restrict__ thw, const float* __restrict__ phw,
    const float* __restrict__ gw, const float* __restrict__ Ww) {
    int i = blockIdx.x * 256 + threadIdx.x;
    if (i < 768 * CC) {
        float v = (i < 131072) ? thw[i] : (i < 262144 ? phw[i - 131072] : gw[i - 262144]);
        bf16 h = __float2bfloat16_rn(v);
        g_w3h[i] = h;
        g_w3l[i] = __float2bfloat16_rn(v - __bfloat162float(h));
    } else {
        int j = i - 768 * CC;
        if (j < CC * CI) g_Wwb[j] = __float2bfloat16_rn(Ww[j]);
    }
}

// ---------------- K3: fused projections (split HMMA, cp.async pipelined) ----------------
__global__ void __launch_bounds__(512, 1) k_proj(
    const float* __restrict__ thb, const float* __restrict__ phb, const float* __restrict__ gb) {
    extern __shared__ char smem[];
    u32 s0 = (s2u(smem) + 127) & ~127u;
    const u32 BUF = 98304;  // Ah 32K | Al 32K | Bh 16K | Bl 16K
    int tid = threadIdx.x, wid = tid >> 5, lane = tid & 31;
    int m0w = (wid >> 2) * 64, n0w = (wid & 3) * 32;
    int lr = lane >> 2, lc = lane & 3;

    int sel = blockIdx.x >> 1, ph0 = (blockIdx.x & 1) * 128;
    size_t m0 = (size_t)blockIdx.y * 256;
    const bf16* Ah = g_fh + m0 * CC;
    const bf16* Al = g_fl + m0 * CC;
    const bf16* Bh = g_w3h + (size_t)(sel * 256 + ph0) * CC;
    const bf16* Bl = g_w3l + (size_t)(sel * 256 + ph0) * CC;

    auto issue = [&](int c) {
        u32 b = s0 + (c & 1) * BUF;
        int kc = c * 64;
        ldtile_async(b,         Ah, CC, kc, 256, tid, 512);
        ldtile_async(b + 32768, Al, CC, kc, 256, tid, 512);
        ldtile_async(b + 65536, Bh, CC, kc, 128, tid, 512);
        ldtile_async(b + 81920, Bl, CC, kc, 128, tid, 512);
        CP_COMMIT();
    };

    float acc[4][4][4] = {};
    issue(0);
    for (int c = 0; c < 8; c++) {
        if (c + 1 < 8) { issue(c + 1); CP_WAIT1(); } else { CP_WAIT0(); }
        __syncthreads();
        u32 b = s0 + (c & 1) * BUF;
        warp_pass3(acc, b, b + 32768, b + 65536, b + 81920, m0w, n0w, lane);
        __syncthreads();
    }

    const float* bias = sel == 0 ? thb : (sel == 1 ? phb : gb);
#pragma unroll
    for (int i = 0; i < 4; i++)
#pragma unroll
        for (int j = 0; j < 4; j++) {
            int nl = n0w + j * 8 + 2 * lc;
            int ng = ph0 + nl;
            float b0 = bias[ng], b1 = bias[ng + 1];
#pragma unroll
            for (int h = 0; h < 2; h++) {
                int m = (int)m0 + m0w + i * 16 + lr + 8 * h;
                float v0 = acc[i][j][2 * h] + b0;
                float v1 = acc[i][j][2 * h + 1] + b1;
                if (sel < 2) {
                    bf16* Dh = sel ? g_phh : g_thh;
                    bf16* Dl = sel ? g_phl : g_thl;
                    bf16 h0 = __float2bfloat16_rn(v0), h1 = __float2bfloat16_rn(v1);
                    bf16 l0 = __float2bfloat16_rn(v0 - __bfloat162float(h0));
                    bf16 l1 = __float2bfloat16_rn(v1 - __bfloat162float(h1));
                    __nv_bfloat162 hp; hp.x = h0; hp.y = h1;
                    __nv_bfloat162 lp; lp.x = l0; lp.y = l1;
                    *(u32*)&Dh[(size_t)m * CI + ng] = *(u32*)&hp;
                    *(u32*)&Dl[(size_t)m * CI + ng] = *(u32*)&lp;
                } else {
                    g_gxT[(size_t)ng * TT + m] = __float2bfloat16_rn(v0);
                    g_gxT[(size_t)(ng + 1) * TT + m] = __float2bfloat16_rn(v1);
                }
            }
        }
}

// ---------------- K4: attn logits (split HMMA, cp.async pipelined) + mask ----------------
__global__ void __launch_bounds__(512, 1) k_attn(float* __restrict__ attn) {
    extern __shared__ char smem[];
    u32 s0 = (s2u(smem) + 127) & ~127u;
    const u32 BUF = 98304;
    int tid = threadIdx.x, wid = tid >> 5, lane = tid & 31;
    int m0w = (wid >> 2) * 64, n0w = (wid & 3) * 32;
    int lr = lane >> 2, lc = lane & 3;

    size_t m0 = (size_t)blockIdx.y * 256;
    size_t n0 = (size_t)blockIdx.x * 128;

    auto issue = [&](int c) {
        u32 b = s0 + (c & 1) * BUF;
        int kc = c * 64;
        ldtile_async(b,         g_thh + m0 * CI, CI, kc, 256, tid, 512);
        ldtile_async(b + 32768, g_thl + m0 * CI, CI, kc, 256, tid, 512);
        ldtile_async(b + 65536, g_phh + n0 * CI, CI, kc, 128, tid, 512);
        ldtile_async(b + 81920, g_phl + n0 * CI, CI, kc, 128, tid, 512);
        CP_COMMIT();
    };

    float acc[4][4][4] = {};
    issue(0);
    for (int c = 0; c < 4; c++) {
        if (c + 1 < 4) { issue(c + 1); CP_WAIT1(); } else { CP_WAIT0(); }
        __syncthreads();
        u32 b = s0 + (c & 1) * BUF;
        warp_pass3(acc, b, b + 32768, b + 65536, b + 81920, m0w, n0w, lane);
        __syncthreads();
    }

#pragma unroll
    for (int i = 0; i < 4; i++)
#pragma unroll
        for (int j = 0; j < 4; j++) {
            int n = (int)n0 + n0w + j * 8 + 2 * lc;
#pragma unroll
            for (int h = 0; h < 2; h++) {
                int m = (int)m0 + m0w + i * 16 + lr + 8 * h;
                int bm = m / NJ;
                float2 o;
                o.x = (n / NJ == bm)       ? -1000.0f : acc[i][j][2 * h];
                o.y = ((n + 1) / NJ == bm) ? -1000.0f : acc[i][j][2 * h + 1];
                *(float2*)&attn[(size_t)m * TT + n] = o;
            }
        }
}

// ---------------- K5: row softmax (in place) + bf16 copy ----------------
__global__ void __launch_bounds__(256) k_softmax(float* __restrict__ attn) {
    __shared__ float red[256];
    int t = threadIdx.x;
    float* p = attn + (size_t)blockIdx.x * TT;
    bf16* pb = g_pb + (size_t)blockIdx.x * TT;
    float v[23];
    float mx = -1e30f;
#pragma unroll
    for (int i = 0; i < 23; i++) { v[i] = p[t + 256 * i]; mx = fmaxf(mx, v[i]); }
    red[t] = mx; __syncthreads();
    for (int s = 128; s > 0; s >>= 1) { if (t < s) red[t] = fmaxf(red[t], red[t + s]); __syncthreads(); }
    mx = red[0]; __syncthreads();
    float sum = 0.0f;
#pragma unroll
    for (int i = 0; i < 23; i++) { v[i] = __expf(v[i] - mx); sum += v[i]; }
    red[t] = sum; __syncthreads();
    for (int s = 128; s > 0; s >>= 1) { if (t < s) red[t] += red[t + s]; __syncthreads(); }
    float inv = 1.0f / red[0];
#pragma unroll
    for (int i = 0; i < 23; i++) {
        float r = v[i] * inv;
        p[t + 256 * i] = r;
        pb[t + 256 * i] = __float2bfloat16_rn(r);
    }
}

// ---------------- K6: y = P @ g_x (bf16 HMMA, M=64 tiles, cp.async pipelined) ----------------
__global__ void __launch_bounds__(256) k_pv() {
    extern __shared__ char smem[];
    u32 s0 = (s2u(smem) + 127) & ~127u;
    const u32 BUF = 24576;  // A 8K | B 16K
    int tid = threadIdx.x, wid = tid >> 5, lane = tid & 31;
    int m0w = (wid >> 2) * 32, n0w = (wid & 3) * 32;
    int lr = lane >> 2, lc = lane & 3;

    size_t m0 = (size_t)blockIdx.y * 64;
    size_t n0 = (size_t)blockIdx.x * 128;

    auto issue = [&](int c) {
        u32 b = s0 + (c & 1) * BUF;
        int kc = c * 64;
        ldtile_async(b,        g_pb + m0 * TT, TT, kc, 64, tid, 256);
        ldtile_async(b + 8192, g_gxT + n0 * TT, TT, kc, 128, tid, 256);
        CP_COMMIT();
    };

    const int CH = TT / 64;  // 92
    float acc[2][4][4] = {};
    issue(0);
    for (int c = 0; c < CH; c++) {
        if (c + 1 < CH) { issue(c + 1); CP_WAIT1(); } else { CP_WAIT0(); }
        __syncthreads();
        u32 b = s0 + (c & 1) * BUF;
        warp_pass<2>(acc, b, b + 8192, m0w, n0w, lane);
        __syncthreads();
    }

#pragma unroll
    for (int i = 0; i < 2; i++)
#pragma unroll
        for (int j = 0; j < 4; j++) {
            int n = (int)n0 + n0w + j * 8 + 2 * lc;
#pragma unroll
            for (int h = 0; h < 2; h++) {
                int m = (int)m0 + m0w + i * 16 + lr + 8 * h;
                __nv_bfloat162 p = __floats2bfloat162_rn(acc[i][j][2 * h], acc[i][j][2 * h + 1]);
                *(u32*)&g_yb[(size_t)m * CI + n] = *(u32*)&p;
            }
        }
}

// ---------------- K7: out = y @ W_w^T + W_b + ori^T (bf16 HMMA) ----------------
__global__ void __launch_bounds__(256, 2) k_out(
    const float* __restrict__ ori, const float* __restrict__ Wb, float* __restrict__ out) {
    extern __shared__ char smem[];
    u32 s0 = (s2u(smem) + 127) & ~127u;
    const u32 sA = s0, sB = s0 + 16384;
    int tid = threadIdx.x, wid = tid >> 5, lane = tid & 31;
    int m0w = (wid >> 2) * 64, n0w = (wid & 3) * 32;
    int lr = lane >> 2, lc = lane & 3;

    size_t m0 = (size_t)blockIdx.y * 128;
    size_t n0 = (size_t)blockIdx.x * 128;

    float acc[4][4][4] = {};
    for (int c = 0; c < 4; c++) {
        int kc = c * 64;
        ldtile(sA, g_yb + m0 * CI, CI, kc, 128, tid);
        ldtile(sB, g_Wwb + n0 * CI, CI, kc, 128, tid);
        __syncthreads();
        warp_pass<4>(acc, sA, sB, m0w, n0w, lane);
        __syncthreads();
    }

#pragma unroll
    for (int i = 0; i < 4; i++)
#pragma unroll
        for (int j = 0; j < 4; j++) {
            int n = (int)n0 + n0w + j * 8 + 2 * lc;
            float b0 = Wb[n], b1 = Wb[n + 1];
#pragma unroll
            for (int h = 0; h < 2; h++) {
                int m = (int)m0 + m0w + i * 16 + lr + 8 * h;
                int nb = m / NJ, jj = m - nb * NJ;
                const float* orow = ori + (size_t)nb * CC * NJ + jj;
                float2 o;
                o.x = acc[i][j][2 * h]     + b0 + orow[(size_t)n * NJ];
                o.y = acc[i][j][2 * h + 1] + b1 + orow[(size_t)(n + 1) * NJ];
                *(float2*)&out[(size_t)m * CC + n] = o;
            }
        }
}

// ---------------- launch ----------------
extern "C" void kernel_launch(void* const* d_in, const int* in_sizes, int n_in,
                              void* d_out, int out_size) {
    const float* ori = (const float*)d_in[0];
    const float* gm  = (const float*)d_in[1];
    const float* bt  = (const float*)d_in[2];
    const float* mn  = (const float*)d_in[3];
    const float* vr  = (const float*)d_in[4];
    const float* thw = (const float*)d_in[5];
    const float* thb = (const float*)d_in[6];
    const float* phw = (const float*)d_in[7];
    const float* phb = (const float*)d_in[8];
    const float* gw  = (const float*)d_in[9];
    const float* gb  = (const float*)d_in[10];
    const float* Ww  = (const float*)d_in[11];
    const float* Wb  = (const float*)d_in[12];

    float* out  = (float*)d_out;
    float* attn = out + (size_t)128 * NJ * CC;

    cudaFuncSetAttribute(k_proj, cudaFuncAttributeMaxDynamicSharedMemorySize, 196736);
    cudaFuncSetAttribute(k_attn, cudaFuncAttributeMaxDynamicSharedMemorySize, 196736);
    cudaFuncSetAttribute(k_pv,   cudaFuncAttributeMaxDynamicSharedMemorySize, 49280);

    k_bnrelu<<<dim3(32, 128), 736>>>(ori, gm, bt, mn, vr);
    k_wsplit<<<2048, 256>>>(thw, phw, gw, Ww);
    k_proj<<<dim3(6, 23), 512, 196736>>>(thb, phb, gb);
    k_attn<<<dim3(46, 23), 512, 196736>>>(attn);
    k_softmax<<<TT, 256>>>(attn);
    k_pv<<<dim3(2, 92), 256, 49280>>>();
    k_out<<<dim3(4, 46), 256, 33024>>>(ori, Wb, out);
}